// round 2
// baseline (speedup 1.0000x reference)
#include <cuda_runtime.h>

// Problem constants
#define BB 512
#define LL 2048
#define HH 64
#define MM 256
#define VV 64
#define RFQ 16
#define NCHUNK 128
#define NB 4          // batches per block
#define NT 256        // threads per block
#define NGRID 128

// Shared memory layout (float offsets)
#define OFF_VP    0            // [3][64 vocab][64 j] = 12288
#define OFF_RVT   12288        // [64 i][192 row]     = 12288
#define OFF_AT    24576        // [64 c][64 i]        = 4096
#define OFF_A0    28672        // [64]
#define OFF_RV0   28736        // [192]
#define OFF_TILE  28928        // 4 * 64*65 = 16640  (also weight staging scratch at start)
#define OFF_HS    45568        // 4 * 2 * 64 = 512 (double-buffered h)
#define OFF_QS    46080        // 4 * 64
#define OFF_SS    46336        // 4 * 64
#define OFF_ES    46592        // 4 * 64
#define OFF_RS    46848        // 4 * 64
#define OFF_TOK   47104        // 4 * 16 ints
#define SMEM_FLOATS 47168      // 188672 bytes

__device__ __forceinline__ void gbar(int id) {
    asm volatile("bar.sync %0, 64;" :: "r"(id) : "memory");
}
__device__ __forceinline__ float sigmoidf_(float x) {
    float e = __expf(-x);
    return __fdividef(1.f, 1.f + e);
}
__device__ __forceinline__ float tanhf_(float x) {
    float e = __expf(2.f * x);
    return 1.f - __fdividef(2.f, e + 1.f);
}

__global__ void __launch_bounds__(NT, 1) ffm_kernel(
    const int*   __restrict__ seq,
    const float* __restrict__ memory,
    const float* __restrict__ embed_w,
    const float* __restrict__ w_ih,
    const float* __restrict__ w_hh,
    const float* __restrict__ b_ih,
    const float* __restrict__ b_hh,
    const float* __restrict__ key_w,
    const float* __restrict__ key_b,
    const float* __restrict__ val_w,
    const float* __restrict__ val_b,
    const float* __restrict__ query_w,
    const float* __restrict__ query_b,
    const float* __restrict__ head_w,
    const float* __restrict__ head_b,
    float* __restrict__ out)
{
    extern __shared__ float sm[];
    float* VP  = sm + OFF_VP;
    float* RVT = sm + OFF_RVT;
    float* AT  = sm + OFF_AT;
    float* A0  = sm + OFF_A0;
    float* RV0 = sm + OFF_RV0;

    const int tid = threadIdx.x;
    const int j   = tid & 63;
    const int bl  = tid >> 6;
    const int bg  = blockIdx.x * NB + bl;
    const float SCALE = 0.125f;  // 1/sqrt(64)

    // ---- Stage small weight matrices into TILE scratch (reused later) ----
    {
        float* stg = sm + OFF_TILE;  // emb@0, val@4096, key@8192, qry@12288
        for (int e = tid; e < 4096; e += NT) {
            stg[e]         = embed_w[e];
            stg[4096 + e]  = val_w[e];
            stg[8192 + e]  = key_w[e];
            stg[12288 + e] = query_w[e];
        }
    }
    __syncthreads();

    // ---- Precompute folded tables ----
    {
        float* stg = sm + OFF_TILE;
        if (tid < 192) {
            const int row = tid;
            const int g = row >> 6, jj = row & 63;
            float wx[64], wv[64];
#pragma unroll
            for (int c = 0; c < 64; c++) {
                wx[c] = w_ih[row * 128 + c];
                wv[c] = w_ih[row * 128 + 64 + c];
            }
            const float bias = b_ih[row];
            // vocab projection table: VP[g][v][jj] = emb[v] . W_ih_x[row] + b_ih[row]
            for (int v = 0; v < 64; v++) {
                float acc = bias;
#pragma unroll
                for (int c = 0; c < 64; c++) acc = fmaf(stg[v * 64 + c], wx[c], acc);
                VP[g * 4096 + v * 64 + jj] = acc;
            }
            // RVT[i][row] = sum_kk W_ih_r[row][kk] * val_w[kk][i]
            for (int i = 0; i < 64; i++) {
                float acc = 0.f;
#pragma unroll
                for (int kk = 0; kk < 64; kk++) acc = fmaf(wv[kk], stg[4096 + kk * 64 + i], acc);
                RVT[i * 192 + row] = acc;
            }
            float acc0 = 0.f;
#pragma unroll
            for (int kk = 0; kk < 64; kk++) acc0 = fmaf(wv[kk], val_b[kk], acc0);
            RV0[row] = acc0;
        }
        // AT[c][i] = scale * sum_kk key_w[kk][i] * query_w[kk][c]
        for (int e = tid; e < 4096; e += NT) {
            const int c = e >> 6, i = e & 63;
            float acc = 0.f;
#pragma unroll
            for (int kk = 0; kk < 64; kk++)
                acc = fmaf(stg[8192 + kk * 64 + i], stg[12288 + kk * 64 + c], acc);
            AT[e] = acc * SCALE;
        }
        if (tid < 64) {
            float acc = 0.f;
#pragma unroll
            for (int kk = 0; kk < 64; kk++) acc = fmaf(stg[8192 + kk * 64 + tid], query_b[kk], acc);
            A0[tid] = acc * SCALE;
        }
    }

    // ---- Load W_hh rows {j, 64+j, 128+j} into registers ----
    float wr[64], wz[64], wn[64];
#pragma unroll
    for (int i = 0; i < 64; i++) {
        wr[i] = w_hh[j * 64 + i];
        wz[i] = w_hh[(64 + j) * 64 + i];
        wn[i] = w_hh[(128 + j) * 64 + i];
    }
    const float bhr = b_hh[j], bhz = b_hh[64 + j], bhn = b_hh[128 + j];

    float* TILEb = sm + OFF_TILE + bl * 4160;   // [64 rows][stride 65]
    float* HSb   = sm + OFF_HS   + bl * 128;    // double buffer
    float* QSb   = sm + OFF_QS   + bl * 64;
    float* SSb   = sm + OFF_SS   + bl * 64;
    float* ESb   = sm + OFF_ES   + bl * 64;
    float* RSb   = sm + OFF_RS   + bl * 64;
    int*   TOKb  = (int*)(sm + OFF_TOK) + bl * 16;

    HSb[j] = 0.f;        // buffer 0 = h0
    float h = 0.f;
    int cur = 0;
    const float* memb = memory + (size_t)bg * (MM * HH);
    const int*   seqb = seq + (size_t)bg * LL;
    const int barid = bl + 1;
    __syncthreads();

    for (int ch = 0; ch < NCHUNK; ch++) {
        const float* hsr = HSb + cur * 64;
        // token prefetch for this chunk
        if (j < 16) TOKb[j] = seqb[ch * RFQ + j];
        // qt[j] = scale * (A h + a0)[j]   (key_b term is constant over m -> cancels)
        float qt = A0[j];
#pragma unroll 8
        for (int c = 0; c < 64; c++) qt = fmaf(AT[c * 64 + j], hsr[c], qt);
        QSb[j] = qt;
        gbar(barid);

        // ---- single pass over memory: online softmax + weighted accumulation ----
        float Mx = -1e30f, D = 0.f, macc = 0.f;
        for (int t4 = 0; t4 < 4; t4++) {
            const float* mt = memb + t4 * 64 * 64;
            // cooperative copy tile (coalesced LDG, conflict-free STS, stride 65)
#pragma unroll 8
            for (int r = 0; r < 64; r++) TILEb[r * 65 + j] = mt[r * 64 + j];
            gbar(barid);
            // score for row m=j of this tile
            float s = 0.f;
#pragma unroll 8
            for (int i = 0; i < 64; i++) s = fmaf(QSb[i], TILEb[j * 65 + i], s);
            SSb[j] = s;
            gbar(barid);
            // tile max (redundant, deterministic)
            float tm = -1e30f;
#pragma unroll 8
            for (int m = 0; m < 64; m++) tm = fmaxf(tm, SSb[m]);
            const float nM = fmaxf(Mx, tm);
            const float alpha = __expf(Mx - nM);
            ESb[j] = __expf(s - nM);
            gbar(barid);
            macc *= alpha; D *= alpha;
#pragma unroll 8
            for (int m = 0; m < 64; m++) {
                const float em = ESb[m];
                macc = fmaf(em, TILEb[m * 65 + j], macc);
                D += em;
            }
            Mx = nM;
            gbar(barid);
        }
        RSb[j] = macc / D;   // normalized weighted memory vector (value-space folded into RVT)
        gbar(barid);

        // r_proj rows {j, 64+j, 128+j} = RVT^T . RSb + RV0
        float rp_r = RV0[j], rp_z = RV0[64 + j], rp_n = RV0[128 + j];
#pragma unroll 8
        for (int i = 0; i < 64; i++) {
            const float rv = RSb[i];
            rp_r = fmaf(RVT[i * 192 + j], rv, rp_r);
            rp_z = fmaf(RVT[i * 192 + 64 + j], rv, rp_z);
            rp_n = fmaf(RVT[i * 192 + 128 + j], rv, rp_n);
        }

        // ---- 16 GRU steps ----
        for (int st = 0; st < RFQ; st++) {
            const int tok = TOKb[st];
            const float gxr = VP[tok * 64 + j] + rp_r;
            const float gxz = VP[4096 + tok * 64 + j] + rp_z;
            const float gxn = VP[8192 + tok * 64 + j] + rp_n;
            const float4* h4 = (const float4*)(HSb + cur * 64);
            float ar = bhr, az = bhz, an = bhn;
#pragma unroll
            for (int i4 = 0; i4 < 16; i4++) {
                const float4 hv = h4[i4];
                ar = fmaf(wr[4 * i4 + 0], hv.x, ar); az = fmaf(wz[4 * i4 + 0], hv.x, az); an = fmaf(wn[4 * i4 + 0], hv.x, an);
                ar = fmaf(wr[4 * i4 + 1], hv.y, ar); az = fmaf(wz[4 * i4 + 1], hv.y, az); an = fmaf(wn[4 * i4 + 1], hv.y, an);
                ar = fmaf(wr[4 * i4 + 2], hv.z, ar); az = fmaf(wz[4 * i4 + 2], hv.z, az); an = fmaf(wn[4 * i4 + 2], hv.z, an);
                ar = fmaf(wr[4 * i4 + 3], hv.w, ar); az = fmaf(wz[4 * i4 + 3], hv.w, az); an = fmaf(wn[4 * i4 + 3], hv.w, an);
            }
            const float r = sigmoidf_(gxr + ar);
            const float z = sigmoidf_(gxz + az);
            const float n = tanhf_(gxn + r * an);
            const float hn = fmaf(z, h - n, n);     // (1-z)n + z h
            HSb[(cur ^ 1) * 64 + j] = hn;
            h = hn;
            gbar(barid);
            cur ^= 1;
        }
    }

    // ---- head ----
    const float* hf = HSb + cur * 64;
    float o = head_b[j];
#pragma unroll 8
    for (int i = 0; i < 64; i++) o = fmaf(head_w[j * 64 + i], hf[i], o);
    out[(size_t)bg * VV + j] = o;
}

extern "C" void kernel_launch(void* const* d_in, const int* in_sizes, int n_in,
                              void* d_out, int out_size) {
    const int*   seq      = (const int*)  d_in[0];
    const float* memory   = (const float*)d_in[1];
    const float* embed_w  = (const float*)d_in[2];
    const float* w_ih     = (const float*)d_in[3];
    const float* w_hh     = (const float*)d_in[4];
    const float* b_ih     = (const float*)d_in[5];
    const float* b_hh     = (const float*)d_in[6];
    const float* key_w    = (const float*)d_in[7];
    const float* key_b    = (const float*)d_in[8];
    const float* val_w    = (const float*)d_in[9];
    const float* val_b    = (const float*)d_in[10];
    const float* query_w  = (const float*)d_in[11];
    const float* query_b  = (const float*)d_in[12];
    const float* head_w   = (const float*)d_in[13];
    const float* head_b   = (const float*)d_in[14];

    const size_t shmem = (size_t)SMEM_FLOATS * sizeof(float);
    cudaFuncSetAttribute(ffm_kernel, cudaFuncAttributeMaxDynamicSharedMemorySize, (int)shmem);
    ffm_kernel<<<NGRID, NT, shmem>>>(seq, memory, embed_w, w_ih, w_hh, b_ih, b_hh,
                                     key_w, key_b, val_w, val_b, query_w, query_b,
                                     head_w, head_b, (float*)d_out);
}

// round 3
// speedup vs baseline: 1.8276x; 1.8276x over previous
#include <cuda_runtime.h>

// Problem constants
#define BB 512
#define LL 2048
#define HH 64
#define MM 256
#define VV 64
#define RFQ 16
#define NCHUNK 128
#define NB 4          // batches per block
#define NT 256        // threads per block
#define NGRID 128

#define TSTRIDE 68    // padded tile row stride (floats): 16B-aligned, conflict-free for
                      // both row-major float4 reads (4j mod 32 distinct per phase) and
                      // column reads (j contiguous)

// Shared memory layout (float offsets)
#define OFF_VP    0            // [3][64 vocab][64 j] = 12288
#define OFF_RVT   12288        // [64 i][192 row]     = 12288
#define OFF_AT    24576        // [64 c][64 i]        = 4096
#define OFF_A0    28672        // [64]
#define OFF_RV0   28736        // [192]
#define OFF_WNJ   28928        // [64 j][stride 68]   = 4352  (W_hh n-gate, row-major per j)
#define OFF_TILE  33280        // 4 * 64*68 = 17408 (also weight staging scratch at start)
#define OFF_HS    50688        // 4 * 2 * 64 = 512 (double-buffered h)
#define OFF_QS    51200        // 4 * 64
#define OFF_SS    51456        // 4 * 64
#define OFF_ES    51712        // 4 * 64
#define OFF_RS    51968        // 4 * 64
#define OFF_TOK   52224        // 4 * 16 ints
#define SMEM_FLOATS 52288      // 209152 bytes

__device__ __forceinline__ void gbar(int id) {
    asm volatile("bar.sync %0, 64;" :: "r"(id) : "memory");
}
__device__ __forceinline__ float sigmoidf_(float x) {
    float e = __expf(-x);
    return __fdividef(1.f, 1.f + e);
}
__device__ __forceinline__ float tanhf_(float x) {
    float e = __expf(2.f * x);
    return 1.f - __fdividef(2.f, e + 1.f);
}

__global__ void __launch_bounds__(NT, 1) ffm_kernel(
    const int*   __restrict__ seq,
    const float* __restrict__ memory,
    const float* __restrict__ embed_w,
    const float* __restrict__ w_ih,
    const float* __restrict__ w_hh,
    const float* __restrict__ b_ih,
    const float* __restrict__ b_hh,
    const float* __restrict__ key_w,
    const float* __restrict__ key_b,
    const float* __restrict__ val_w,
    const float* __restrict__ val_b,
    const float* __restrict__ query_w,
    const float* __restrict__ query_b,
    const float* __restrict__ head_w,
    const float* __restrict__ head_b,
    float* __restrict__ out)
{
    extern __shared__ float sm[];
    float* VP  = sm + OFF_VP;
    float* RVT = sm + OFF_RVT;
    float* AT  = sm + OFF_AT;
    float* A0  = sm + OFF_A0;
    float* RV0 = sm + OFF_RV0;
    float* WNJ = sm + OFF_WNJ;

    const int tid = threadIdx.x;
    const int j   = tid & 63;
    const int bl  = tid >> 6;
    const int bg  = blockIdx.x * NB + bl;
    const float SCALE = 0.125f;  // 1/sqrt(64)

    // ---- Stage small weight matrices into TILE scratch (reused later) ----
    {
        float* stg = sm + OFF_TILE;  // emb@0, val@4096, key@8192, qry@12288
        for (int e = tid; e < 4096; e += NT) {
            stg[e]         = embed_w[e];
            stg[4096 + e]  = val_w[e];
            stg[8192 + e]  = key_w[e];
            stg[12288 + e] = query_w[e];
        }
        // W_hh n-gate rows into padded shared array: WNJ[j][i]
        for (int e = tid; e < 4096; e += NT) {
            const int jj = e >> 6, i = e & 63;
            WNJ[jj * TSTRIDE + i] = w_hh[(128 + jj) * 64 + i];
        }
    }
    __syncthreads();

    // ---- Precompute folded tables ----
    {
        float* stg = sm + OFF_TILE;
        if (tid < 192) {
            const int row = tid;
            const int g = row >> 6, jj = row & 63;
            float wx[64], wv[64];
#pragma unroll
            for (int c = 0; c < 64; c++) {
                wx[c] = w_ih[row * 128 + c];
                wv[c] = w_ih[row * 128 + 64 + c];
            }
            const float bias = b_ih[row];
            // vocab projection table: VP[g][v][jj] = emb[v] . W_ih_x[row] + b_ih[row]
            for (int v = 0; v < 64; v++) {
                float acc = bias;
#pragma unroll
                for (int c = 0; c < 64; c++) acc = fmaf(stg[v * 64 + c], wx[c], acc);
                VP[g * 4096 + v * 64 + jj] = acc;
            }
            // RVT[i][row] = sum_kk W_ih_r[row][kk] * val_w[kk][i]
            for (int i = 0; i < 64; i++) {
                float acc = 0.f;
#pragma unroll
                for (int kk = 0; kk < 64; kk++) acc = fmaf(wv[kk], stg[4096 + kk * 64 + i], acc);
                RVT[i * 192 + row] = acc;
            }
            float acc0 = 0.f;
#pragma unroll
            for (int kk = 0; kk < 64; kk++) acc0 = fmaf(wv[kk], val_b[kk], acc0);
            RV0[row] = acc0;
        }
        // AT[c][i] = scale * sum_kk key_w[kk][i] * query_w[kk][c]
        for (int e = tid; e < 4096; e += NT) {
            const int c = e >> 6, i = e & 63;
            float acc = 0.f;
#pragma unroll
            for (int kk = 0; kk < 64; kk++)
                acc = fmaf(stg[8192 + kk * 64 + i], stg[12288 + kk * 64 + c], acc);
            AT[e] = acc * SCALE;
        }
        if (tid < 64) {
            float acc = 0.f;
#pragma unroll
            for (int kk = 0; kk < 64; kk++) acc = fmaf(stg[8192 + kk * 64 + tid], query_b[kk], acc);
            A0[tid] = acc * SCALE;
        }
    }

    // ---- Load W_hh rows {j, 64+j} (r,z gates) into registers; n gate lives in shared ----
    float wr[64], wz[64];
#pragma unroll
    for (int i = 0; i < 64; i++) {
        wr[i] = w_hh[j * 64 + i];
        wz[i] = w_hh[(64 + j) * 64 + i];
    }
    const float bhr = b_hh[j], bhz = b_hh[64 + j], bhn = b_hh[128 + j];

    float* TILEb = sm + OFF_TILE + bl * (64 * TSTRIDE);   // [64 rows][stride 68]
    float* HSb   = sm + OFF_HS   + bl * 128;              // double buffer
    float* QSb   = sm + OFF_QS   + bl * 64;
    float* SSb   = sm + OFF_SS   + bl * 64;
    float* ESb   = sm + OFF_ES   + bl * 64;
    float* RSb   = sm + OFF_RS   + bl * 64;
    int*   TOKb  = (int*)(sm + OFF_TOK) + bl * 16;

    HSb[j] = 0.f;        // buffer 0 = h0
    float h = 0.f;
    int cur = 0;
    const float* memb = memory + (size_t)bg * (MM * HH);
    const int*   seqb = seq + (size_t)bg * LL;
    const int barid = bl + 1;
    const float4* wn4 = (const float4*)(WNJ + j * TSTRIDE);
    __syncthreads();

    for (int ch = 0; ch < NCHUNK; ch++) {
        const float* hsr = HSb + cur * 64;
        // token prefetch for this chunk
        if (j < 16) TOKb[j] = seqb[ch * RFQ + j];
        // qt[j] = scale * (A h + a0)[j]   (key_b term is constant over m -> cancels)
        float qt = A0[j];
#pragma unroll 8
        for (int c = 0; c < 64; c++) qt = fmaf(AT[c * 64 + j], hsr[c], qt);
        QSb[j] = qt;
        gbar(barid);

        // ---- single pass over memory: online softmax + weighted accumulation ----
        float Mx = -1e30f, D = 0.f, macc = 0.f;
        for (int t4 = 0; t4 < 4; t4++) {
            const float4* mt4 = (const float4*)(memb + t4 * 64 * 64);
            // cooperative vectorized tile copy: coalesced LDG.128, aligned STS.128
#pragma unroll
            for (int it = 0; it < 16; it++) {
                const int e4 = it * 64 + j;          // float4 index in [0,1024)
                const int r = e4 >> 4, c4 = e4 & 15;
                *(float4*)(TILEb + r * TSTRIDE + c4 * 4) = mt4[e4];
            }
            gbar(barid);
            // score for row m=j of this tile (vectorized)
            float s = 0.f;
            {
                const float4* q4 = (const float4*)QSb;            // broadcast
                const float4* row4 = (const float4*)(TILEb + j * TSTRIDE);
#pragma unroll
                for (int i4 = 0; i4 < 16; i4++) {
                    const float4 qv = q4[i4], rv = row4[i4];
                    s = fmaf(qv.x, rv.x, s); s = fmaf(qv.y, rv.y, s);
                    s = fmaf(qv.z, rv.z, s); s = fmaf(qv.w, rv.w, s);
                }
            }
            SSb[j] = s;
            gbar(barid);
            // tile max (redundant, deterministic)
            float tm = -1e30f;
#pragma unroll 8
            for (int m = 0; m < 64; m++) tm = fmaxf(tm, SSb[m]);
            const float nM = fmaxf(Mx, tm);
            const float alpha = __expf(Mx - nM);
            ESb[j] = __expf(s - nM);
            gbar(barid);
            macc *= alpha; D *= alpha;
#pragma unroll 8
            for (int m = 0; m < 64; m++) {
                const float em = ESb[m];
                macc = fmaf(em, TILEb[m * TSTRIDE + j], macc);
                D += em;
            }
            Mx = nM;
            gbar(barid);
        }
        RSb[j] = macc / D;   // normalized weighted memory vector (value-space folded into RVT)
        gbar(barid);

        // r_proj rows {j, 64+j, 128+j} = RVT^T . RSb + RV0
        float rp_r = RV0[j], rp_z = RV0[64 + j], rp_n = RV0[128 + j];
#pragma unroll 8
        for (int i = 0; i < 64; i++) {
            const float rv = RSb[i];
            rp_r = fmaf(RVT[i * 192 + j], rv, rp_r);
            rp_z = fmaf(RVT[i * 192 + 64 + j], rv, rp_z);
            rp_n = fmaf(RVT[i * 192 + 128 + j], rv, rp_n);
        }

        // ---- 16 GRU steps ----
        for (int st = 0; st < RFQ; st++) {
            const int tok = TOKb[st];
            const float gxr = VP[tok * 64 + j] + rp_r;
            const float gxz = VP[4096 + tok * 64 + j] + rp_z;
            const float gxn = VP[8192 + tok * 64 + j] + rp_n;
            const float4* h4 = (const float4*)(HSb + cur * 64);   // broadcast reads
            float ar = bhr, az = bhz, an = bhn;
#pragma unroll
            for (int i4 = 0; i4 < 16; i4++) {
                const float4 hv = h4[i4];
                const float4 wv = wn4[i4];
                ar = fmaf(wr[4 * i4 + 0], hv.x, ar); az = fmaf(wz[4 * i4 + 0], hv.x, az); an = fmaf(wv.x, hv.x, an);
                ar = fmaf(wr[4 * i4 + 1], hv.y, ar); az = fmaf(wz[4 * i4 + 1], hv.y, az); an = fmaf(wv.y, hv.y, an);
                ar = fmaf(wr[4 * i4 + 2], hv.z, ar); az = fmaf(wz[4 * i4 + 2], hv.z, az); an = fmaf(wv.z, hv.z, an);
                ar = fmaf(wr[4 * i4 + 3], hv.w, ar); az = fmaf(wz[4 * i4 + 3], hv.w, az); an = fmaf(wv.w, hv.w, an);
            }
            const float r = sigmoidf_(gxr + ar);
            const float z = sigmoidf_(gxz + az);
            const float n = tanhf_(gxn + r * an);
            const float hn = fmaf(z, h - n, n);     // (1-z)n + z h
            HSb[(cur ^ 1) * 64 + j] = hn;
            h = hn;
            gbar(barid);
            cur ^= 1;
        }
    }

    // ---- head ----
    const float* hf = HSb + cur * 64;
    float o = head_b[j];
#pragma unroll 8
    for (int i = 0; i < 64; i++) o = fmaf(head_w[j * 64 + i], hf[i], o);
    out[(size_t)bg * VV + j] = o;
}

extern "C" void kernel_launch(void* const* d_in, const int* in_sizes, int n_in,
                              void* d_out, int out_size) {
    const int*   seq      = (const int*)  d_in[0];
    const float* memory   = (const float*)d_in[1];
    const float* embed_w  = (const float*)d_in[2];
    const float* w_ih     = (const float*)d_in[3];
    const float* w_hh     = (const float*)d_in[4];
    const float* b_ih     = (const float*)d_in[5];
    const float* b_hh     = (const float*)d_in[6];
    const float* key_w    = (const float*)d_in[7];
    const float* key_b    = (const float*)d_in[8];
    const float* val_w    = (const float*)d_in[9];
    const float* val_b    = (const float*)d_in[10];
    const float* query_w  = (const float*)d_in[11];
    const float* query_b  = (const float*)d_in[12];
    const float* head_w   = (const float*)d_in[13];
    const float* head_b   = (const float*)d_in[14];

    const size_t shmem = (size_t)SMEM_FLOATS * sizeof(float);
    cudaFuncSetAttribute(ffm_kernel, cudaFuncAttributeMaxDynamicSharedMemorySize, (int)shmem);
    ffm_kernel<<<NGRID, NT, shmem>>>(seq, memory, embed_w, w_ih, w_hh, b_ih, b_hh,
                                     key_w, key_b, val_w, val_b, query_w, query_b,
                                     head_w, head_b, (float*)d_out);
}